// round 1
// baseline (speedup 1.0000x reference)
#include <cuda_runtime.h>
#include <cstring>

typedef unsigned long long u64;

#define N_MAX   400000
#define CIN     32
#define COUT    64
#define OZ      100
#define OY      100
#define OX      8
#define NUM_OUT (2*OZ*OY*OX)           /* 160000 */
#define MAXP    (8*N_MAX)              /* 3.2M max pairs */
#define PPB     2048                   /* pairs per gemm block */
#define MAXCHUNK ((N_MAX + PPB - 1)/PPB)

/* ------------------ device scratch (static, no allocs) ------------------ */
__device__ int      g_hist[65536];
__device__ int      g_sel[2];          /* [0]=top16 bin, [1]=residual rank */
__device__ unsigned g_thr;             /* exact threshold key */
__device__ int      g_offcnt[27];
__device__ int      g_offstart[28];
__device__ int      g_cursor[27];
__device__ int      g_keep[NUM_OUT];
__device__ int      g_pair_idx[MAXP];
__device__ int      g_pair_vox[MAXP];

/* ------------------ helpers ------------------ */
__device__ __forceinline__ unsigned fkey(float x) {
    unsigned u = __float_as_uint(x);
    return (u & 0x80000000u) ? ~u : (u | 0x80000000u);
}

__device__ __forceinline__ u64 ffma2(u64 a, u64 b, u64 c) {
    u64 d;
    asm("fma.rn.f32x2 %0, %1, %2, %3;" : "=l"(d) : "l"(a), "l"(b), "l"(c));
    return d;
}
__device__ __forceinline__ u64 fadd2(u64 a, u64 b) {
    u64 d;
    asm("add.rn.f32x2 %0, %1, %2;" : "=l"(d) : "l"(a), "l"(b));
    return d;
}
__device__ __forceinline__ u64 dup2(float v) {
    float2 t = make_float2(v, v);
    u64 r; memcpy(&r, &t, 8); return r;
}

/* enumerate valid (offset, output voxel) pairs for one point: <= 8 */
__device__ __forceinline__ int enum_off(int b, int z, int y, int x, int* ol, int* vl) {
    int zo[2], zc[2]; int nzc = 0;
    int yo[2], yc[2]; int nyc = 0;
    int xo[2], xc[2]; int nxc = 0;
#pragma unroll
    for (int o = 0; o < 3; o++) {
        int nz = z + 1 - o;
        if (nz >= 0 && !(nz & 1)) { int c = nz >> 1; if (c < OZ) { zo[nzc] = o; zc[nzc] = c; nzc++; } }
        int ny = y + 1 - o;
        if (ny >= 0 && !(ny & 1)) { int c = ny >> 1; if (c < OY) { yo[nyc] = o; yc[nyc] = c; nyc++; } }
        int nx = x + 1 - o;
        if (nx >= 0 && !(nx & 1)) { int c = nx >> 1; if (c < OX) { xo[nxc] = o; xc[nxc] = c; nxc++; } }
    }
    int cnt = 0;
    for (int iz = 0; iz < nzc; iz++)
        for (int iy = 0; iy < nyc; iy++)
            for (int ix = 0; ix < nxc; ix++) {
                ol[cnt] = (zo[iz]*3 + yo[iy])*3 + xo[ix];
                vl[cnt] = ((b*OZ + zc[iz])*OY + yc[iy])*OX + xc[ix];
                cnt++;
            }
    return cnt;
}

/* ------------------ phase 0: zero scratch ------------------ */
#define TOTZ (65536 + 27 + NUM_OUT)
__global__ void init_zero() {
    int i = blockIdx.x * blockDim.x + threadIdx.x;
    if (i < 65536)              g_hist[i] = 0;
    else if (i < 65536 + 27)    g_offcnt[i - 65536] = 0;
    else if (i < TOTZ)          g_keep[i - 65536 - 27] = 0;
}

/* ------------------ phase 1: exact rank-k select (2-pass radix-16) ------------------ */
__global__ void hist_top16(const float* __restrict__ mask, int n) {
    int i = blockIdx.x * blockDim.x + threadIdx.x;
    if (i < n) {
        unsigned u = fkey(mask[i]);
        atomicAdd(&g_hist[u >> 16], 1);
    }
}
__global__ void hist_low16(const float* __restrict__ mask, int n) {
    int i = blockIdx.x * blockDim.x + threadIdx.x;
    if (i < n) {
        unsigned u = fkey(mask[i]);
        if ((int)(u >> 16) == g_sel[0]) atomicAdd(&g_hist[u & 0xFFFFu], 1);
    }
}
__global__ void select_pass(int pass, int k) {
    __shared__ int s[256];
    int t = threadIdx.x;
    int sum = 0;
    for (int j = 0; j < 256; j++) sum += g_hist[t*256 + j];
    s[t] = sum;
    __syncthreads();
    /* inclusive Hillis-Steele scan */
    for (int off = 1; off < 256; off <<= 1) {
        int v = (t >= off) ? s[t - off] : 0;
        __syncthreads();
        s[t] += v;
        __syncthreads();
    }
    int rank = (pass == 0) ? k : g_sel[1];
    int incl = s[t];
    int excl = incl - sum;
    if (rank >= excl && rank < incl) {
        int cum = excl;
        int bin = t * 256;
        for (int j = 0; j < 256; j++) {
            int h = g_hist[t*256 + j];
            if (rank < cum + h) { bin = t*256 + j; break; }
            cum += h;
        }
        if (pass == 0) { g_sel[0] = bin; g_sel[1] = rank - cum; }
        else           { g_thr = ((unsigned)g_sel[0] << 16) | (unsigned)bin; }
    }
    __syncthreads();
    for (int j = 0; j < 256; j++) g_hist[t*256 + j] = 0;  /* ready for next pass */
}

/* ------------------ phase 2: rulebook ------------------ */
__global__ void count_pairs(const int* __restrict__ coors, int n) {
    __shared__ int s[27];
    if (threadIdx.x < 27) s[threadIdx.x] = 0;
    __syncthreads();
    int i = blockIdx.x * blockDim.x + threadIdx.x;
    if (i < n) {
        int4 c = ((const int4*)coors)[i];
        int ol[8], vl[8];
        int cnt = enum_off(c.x, c.y, c.z, c.w, ol, vl);
        for (int e = 0; e < cnt; e++) atomicAdd(&s[ol[e]], 1);
    }
    __syncthreads();
    if (threadIdx.x < 27 && s[threadIdx.x]) atomicAdd(&g_offcnt[threadIdx.x], s[threadIdx.x]);
}

__global__ void prefix27() {
    if (threadIdx.x == 0) {
        int a = 0;
        for (int o = 0; o < 27; o++) {
            g_offstart[o] = a; g_cursor[o] = a; a += g_offcnt[o];
        }
        g_offstart[27] = a;
    }
}

__global__ void fill_pairs(const int* __restrict__ coors, const float* __restrict__ mask, int n) {
    __shared__ int s[27];
    __shared__ int sbase[27];
    if (threadIdx.x < 27) s[threadIdx.x] = 0;
    __syncthreads();
    int i = blockIdx.x * blockDim.x + threadIdx.x;
    int ol[8], vl[8], rk[8];
    int cnt = 0;
    if (i < n) {
        int4 c = ((const int4*)coors)[i];
        cnt = enum_off(c.x, c.y, c.z, c.w, ol, vl);
        for (int e = 0; e < cnt; e++) rk[e] = atomicAdd(&s[ol[e]], 1);
    }
    __syncthreads();
    if (threadIdx.x < 27) {
        int c = s[threadIdx.x];
        sbase[threadIdx.x] = c ? atomicAdd(&g_cursor[threadIdx.x], c) : 0;
    }
    __syncthreads();
    if (i < n) {
        bool imp = fkey(mask[i]) >= g_thr;
        for (int e = 0; e < cnt; e++) {
            int pos = sbase[ol[e]] + rk[e];
            g_pair_idx[pos] = i;
            g_pair_vox[pos] = vl[e];
            if (imp) g_keep[vl[e]] = 1;   /* idempotent racing store */
        }
    }
}

/* ------------------ phase 3: per-offset gathered GEMM + scatter ------------------ */
__global__ __launch_bounds__(256, 2)
void gemm_scatter(const float* __restrict__ F, const float* __restrict__ W,
                  float* __restrict__ out) {
    int o = blockIdx.x;
    int s = g_offstart[o];
    int e = g_offstart[o + 1];
    int cb = s + blockIdx.y * PPB;
    if (cb >= e) return;
    int ce = min(cb + PPB, e);

    int warp = threadIdx.x >> 5;
    int lane = threadIdx.x & 31;

    /* weight column for channels (2*lane, 2*lane+1), resident in registers */
    u64 w[32];
    const float* Wo = W + o * (CIN * COUT);
#pragma unroll
    for (int k = 0; k < 32; k++)
        w[k] = *reinterpret_cast<const u64*>(Wo + k * COUT + 2 * lane);

    __shared__ u64 sf[8][2][32];   /* per-warp double-buffered feature, f32x2-duplicated */

    int p = cb + warp;
    /* prime buffer 0 */
    {
        float v = 0.f;
        if (p < ce) {
            int idx = g_pair_idx[p];
            v = F[idx * CIN + lane];
        }
        sf[warp][0][lane] = dup2(v);
    }
    int buf = 0;
    for (; p < ce; p += 8) {
        int vox = g_pair_vox[p];
        int pn = p + 8;
        float vn = 0.f;
        if (pn < ce) {
            int idxn = g_pair_idx[pn];
            vn = F[idxn * CIN + lane];
        }
        __syncwarp();
        const u64* fb = sf[warp][buf];
        u64 a0 = 0ull, a1 = 0ull;
#pragma unroll
        for (int k = 0; k < 32; k += 2) {
            a0 = ffma2(fb[k],     w[k],     a0);
            a1 = ffma2(fb[k + 1], w[k + 1], a1);
        }
        u64 acc = fadd2(a0, a1);
        float2 r; memcpy(&r, &acc, 8);
        float* dst = out + vox * COUT + 2 * lane;
        atomicAdd(dst,     r.x);
        atomicAdd(dst + 1, r.y);
        buf ^= 1;
        sf[warp][buf][lane] = dup2(vn);  /* next iter's __syncwarp orders this vs reads */
    }
}

/* ------------------ phase 4: zero rows without important contributors ------------------ */
__global__ void mask_out(float* __restrict__ out) {
    int i = blockIdx.x * blockDim.x + threadIdx.x;   /* over NUM_OUT*16 float4s */
    if (i >= NUM_OUT * 16) return;
    int v = i >> 4;
    if (!g_keep[v]) ((float4*)out)[i] = make_float4(0.f, 0.f, 0.f, 0.f);
}

/* ------------------ launch ------------------ */
extern "C" void kernel_launch(void* const* d_in, const int* in_sizes, int n_in,
                              void* d_out, int out_size) {
    const float* F = (const float*)d_in[0];   /* features [N,32] */
    const int*   C = (const int*)  d_in[1];   /* coors    [N,4]  */
    const float* M = (const float*)d_in[2];   /* mask     [N]    */
    const float* W = (const float*)d_in[3];   /* weight   [3,3,3,32,64] */
    float* out = (float*)d_out;

    int n = in_sizes[2];                      /* N = 400000 */
    int k = (int)((double)n * 0.5);           /* rank for threshold */
    int gpts = (n + 255) / 256;

    cudaMemsetAsync(out, 0, (size_t)out_size * sizeof(float));
    init_zero<<<(TOTZ + 255) / 256, 256>>>();

    hist_top16<<<gpts, 256>>>(M, n);
    select_pass<<<1, 256>>>(0, k);
    hist_low16<<<gpts, 256>>>(M, n);
    select_pass<<<1, 256>>>(1, 0);

    count_pairs<<<gpts, 256>>>(C, n);
    prefix27<<<1, 32>>>();
    fill_pairs<<<gpts, 256>>>(C, M, n);

    gemm_scatter<<<dim3(27, MAXCHUNK), 256>>>(F, W, out);

    mask_out<<<(NUM_OUT * 16 + 255) / 256, 256>>>(out);
}

// round 2
// speedup vs baseline: 1.0220x; 1.0220x over previous
#include <cuda_runtime.h>
#include <cstring>

typedef unsigned long long u64;

#define N_MAX   400000
#define CIN     32
#define COUT    64
#define OZ      100
#define OY      100
#define OX      8
#define NUM_OUT (2*OZ*OY*OX)           /* 160000 */
#define MAXP    (8*N_MAX)              /* 3.2M max pairs */
#define PPB     2048                   /* pairs per gemm block */
#define MAXCHUNK ((N_MAX + PPB - 1)/PPB)

/* ------------------ device scratch (static, no allocs) ------------------ */
__device__ int      g_hist[65536];
__device__ int      g_sel[2];          /* [0]=top16 bin, [1]=residual rank */
__device__ unsigned g_thr;             /* exact threshold key */
__device__ int      g_offcnt[27];
__device__ int      g_offstart[28];
__device__ int      g_cursor[27];
__device__ int      g_keep[NUM_OUT];
__device__ int      g_pair_idx[MAXP];
__device__ int      g_pair_vox[MAXP];

/* ------------------ helpers ------------------ */
__device__ __forceinline__ unsigned fkey(float x) {
    unsigned u = __float_as_uint(x);
    return (u & 0x80000000u) ? ~u : (u | 0x80000000u);
}

__device__ __forceinline__ u64 ffma2(u64 a, u64 b, u64 c) {
    u64 d;
    asm("fma.rn.f32x2 %0, %1, %2, %3;" : "=l"(d) : "l"(a), "l"(b), "l"(c));
    return d;
}
__device__ __forceinline__ u64 fadd2(u64 a, u64 b) {
    u64 d;
    asm("add.rn.f32x2 %0, %1, %2;" : "=l"(d) : "l"(a), "l"(b));
    return d;
}
__device__ __forceinline__ u64 dup2(float v) {
    float2 t = make_float2(v, v);
    u64 r; memcpy(&r, &t, 8); return r;
}

/* enumerate valid (offset, output voxel) pairs for one point: <= 8 */
__device__ __forceinline__ int enum_off(int b, int z, int y, int x, int* ol, int* vl) {
    int zo[2], zc[2]; int nzc = 0;
    int yo[2], yc[2]; int nyc = 0;
    int xo[2], xc[2]; int nxc = 0;
#pragma unroll
    for (int o = 0; o < 3; o++) {
        int nz = z + 1 - o;
        if (nz >= 0 && !(nz & 1)) { int c = nz >> 1; if (c < OZ) { zo[nzc] = o; zc[nzc] = c; nzc++; } }
        int ny = y + 1 - o;
        if (ny >= 0 && !(ny & 1)) { int c = ny >> 1; if (c < OY) { yo[nyc] = o; yc[nyc] = c; nyc++; } }
        int nx = x + 1 - o;
        if (nx >= 0 && !(nx & 1)) { int c = nx >> 1; if (c < OX) { xo[nxc] = o; xc[nxc] = c; nxc++; } }
    }
    int cnt = 0;
    for (int iz = 0; iz < nzc; iz++)
        for (int iy = 0; iy < nyc; iy++)
            for (int ix = 0; ix < nxc; ix++) {
                ol[cnt] = (zo[iz]*3 + yo[iy])*3 + xo[ix];
                vl[cnt] = ((b*OZ + zc[iz])*OY + yc[iy])*OX + xc[ix];
                cnt++;
            }
    return cnt;
}

/* ------------------ phase 0: zero scratch ------------------ */
#define TOTZ (65536 + 27 + NUM_OUT)
__global__ void init_zero() {
    int i = blockIdx.x * blockDim.x + threadIdx.x;
    if (i < 65536)              g_hist[i] = 0;
    else if (i < 65536 + 27)    g_offcnt[i - 65536] = 0;
    else if (i < TOTZ)          g_keep[i - 65536 - 27] = 0;
}

/* ------------------ phase 1: exact rank-k select (2-pass radix-16) ------------------ */
__global__ void hist_top16(const float* __restrict__ mask, int n) {
    int i = blockIdx.x * blockDim.x + threadIdx.x;
    if (i < n) {
        unsigned u = fkey(mask[i]);
        atomicAdd(&g_hist[u >> 16], 1);
    }
}
__global__ void hist_low16(const float* __restrict__ mask, int n) {
    int i = blockIdx.x * blockDim.x + threadIdx.x;
    if (i < n) {
        unsigned u = fkey(mask[i]);
        if ((int)(u >> 16) == g_sel[0]) atomicAdd(&g_hist[u & 0xFFFFu], 1);
    }
}
__global__ void select_pass(int pass, int k) {
    __shared__ int s[256];
    int t = threadIdx.x;
    int sum = 0;
    for (int j = 0; j < 256; j++) sum += g_hist[t*256 + j];
    s[t] = sum;
    __syncthreads();
    /* inclusive Hillis-Steele scan */
    for (int off = 1; off < 256; off <<= 1) {
        int v = (t >= off) ? s[t - off] : 0;
        __syncthreads();
        s[t] += v;
        __syncthreads();
    }
    int rank = (pass == 0) ? k : g_sel[1];
    int incl = s[t];
    int excl = incl - sum;
    if (rank >= excl && rank < incl) {
        int cum = excl;
        int bin = t * 256;
        for (int j = 0; j < 256; j++) {
            int h = g_hist[t*256 + j];
            if (rank < cum + h) { bin = t*256 + j; break; }
            cum += h;
        }
        if (pass == 0) { g_sel[0] = bin; g_sel[1] = rank - cum; }
        else           { g_thr = ((unsigned)g_sel[0] << 16) | (unsigned)bin; }
    }
    __syncthreads();
    for (int j = 0; j < 256; j++) g_hist[t*256 + j] = 0;  /* ready for next pass */
}

/* ------------------ phase 2: rulebook ------------------ */
__global__ void count_pairs(const int* __restrict__ coors, int n) {
    __shared__ int s[27];
    if (threadIdx.x < 27) s[threadIdx.x] = 0;
    __syncthreads();
    int i = blockIdx.x * blockDim.x + threadIdx.x;
    if (i < n) {
        int4 c = ((const int4*)coors)[i];
        int ol[8], vl[8];
        int cnt = enum_off(c.x, c.y, c.z, c.w, ol, vl);
        for (int e = 0; e < cnt; e++) atomicAdd(&s[ol[e]], 1);
    }
    __syncthreads();
    if (threadIdx.x < 27 && s[threadIdx.x]) atomicAdd(&g_offcnt[threadIdx.x], s[threadIdx.x]);
}

__global__ void prefix27() {
    if (threadIdx.x == 0) {
        int a = 0;
        for (int o = 0; o < 27; o++) {
            g_offstart[o] = a; g_cursor[o] = a; a += g_offcnt[o];
        }
        g_offstart[27] = a;
    }
}

__global__ void fill_pairs(const int* __restrict__ coors, const float* __restrict__ mask, int n) {
    __shared__ int s[27];
    __shared__ int sbase[27];
    if (threadIdx.x < 27) s[threadIdx.x] = 0;
    __syncthreads();
    int i = blockIdx.x * blockDim.x + threadIdx.x;
    int ol[8], vl[8], rk[8];
    int cnt = 0;
    if (i < n) {
        int4 c = ((const int4*)coors)[i];
        cnt = enum_off(c.x, c.y, c.z, c.w, ol, vl);
        for (int e = 0; e < cnt; e++) rk[e] = atomicAdd(&s[ol[e]], 1);
    }
    __syncthreads();
    if (threadIdx.x < 27) {
        int c = s[threadIdx.x];
        sbase[threadIdx.x] = c ? atomicAdd(&g_cursor[threadIdx.x], c) : 0;
    }
    __syncthreads();
    if (i < n) {
        bool imp = fkey(mask[i]) >= g_thr;
        for (int e = 0; e < cnt; e++) {
            int pos = sbase[ol[e]] + rk[e];
            g_pair_idx[pos] = i;
            g_pair_vox[pos] = vl[e];
            if (imp) g_keep[vl[e]] = 1;   /* idempotent racing store */
        }
    }
}

/* ------------------ phase 3: per-offset gathered GEMM + scatter ------------------ */
__global__ __launch_bounds__(256, 2)
void gemm_scatter(const float* __restrict__ F, const float* __restrict__ W,
                  float* __restrict__ out) {
    int o = blockIdx.x;
    int s = g_offstart[o];
    int e = g_offstart[o + 1];
    int cb = s + blockIdx.y * PPB;
    if (cb >= e) return;
    int ce = min(cb + PPB, e);

    int warp = threadIdx.x >> 5;
    int lane = threadIdx.x & 31;

    /* weight column for channels (2*lane, 2*lane+1), resident in registers */
    u64 w[32];
    const float* Wo = W + o * (CIN * COUT);
#pragma unroll
    for (int k = 0; k < 32; k++)
        w[k] = *reinterpret_cast<const u64*>(Wo + k * COUT + 2 * lane);

    __shared__ u64 sf[8][2][32];   /* per-warp double-buffered feature, f32x2-duplicated */

    int p = cb + warp;
    /* prime buffer 0 */
    {
        float v = 0.f;
        if (p < ce) {
            int idx = g_pair_idx[p];
            v = F[idx * CIN + lane];
        }
        sf[warp][0][lane] = dup2(v);
    }
    int buf = 0;
    for (; p < ce; p += 8) {
        int vox = g_pair_vox[p];
        int pn = p + 8;
        float vn = 0.f;
        if (pn < ce) {
            int idxn = g_pair_idx[pn];
            vn = F[idxn * CIN + lane];
        }
        __syncwarp();
        const u64* fb = sf[warp][buf];
        /* 4 accumulation chains for ILP */
        u64 a0 = 0ull, a1 = 0ull, a2 = 0ull, a3 = 0ull;
#pragma unroll
        for (int k = 0; k < 32; k += 4) {
            a0 = ffma2(fb[k],     w[k],     a0);
            a1 = ffma2(fb[k + 1], w[k + 1], a1);
            a2 = ffma2(fb[k + 2], w[k + 2], a2);
            a3 = ffma2(fb[k + 3], w[k + 3], a3);
        }
        u64 acc = fadd2(fadd2(a0, a1), fadd2(a2, a3));

        /* pair with neighbor lane to form a contiguous float4, then one
           red.global.add.v4.f32 from the 16 even lanes (4x fewer lane-ops) */
        u64 other = __shfl_xor_sync(0xFFFFFFFFu, acc, 1);
        if ((lane & 1) == 0) {
            float2 mine, theirs;
            memcpy(&mine, &acc, 8);
            memcpy(&theirs, &other, 8);
            float* dst = out + vox * COUT + (lane >> 1) * 4;
            asm volatile("red.global.add.v4.f32 [%0], {%1, %2, %3, %4};"
                         :: "l"(dst), "f"(mine.x), "f"(mine.y),
                            "f"(theirs.x), "f"(theirs.y)
                         : "memory");
        }

        buf ^= 1;
        sf[warp][buf][lane] = dup2(vn);  /* next iter's __syncwarp orders this vs reads */
    }
}

/* ------------------ phase 4: zero rows without important contributors ------------------ */
__global__ void mask_out(float* __restrict__ out) {
    int i = blockIdx.x * blockDim.x + threadIdx.x;   /* over NUM_OUT*16 float4s */
    if (i >= NUM_OUT * 16) return;
    int v = i >> 4;
    if (!g_keep[v]) ((float4*)out)[i] = make_float4(0.f, 0.f, 0.f, 0.f);
}

/* ------------------ launch ------------------ */
extern "C" void kernel_launch(void* const* d_in, const int* in_sizes, int n_in,
                              void* d_out, int out_size) {
    const float* F = (const float*)d_in[0];   /* features [N,32] */
    const int*   C = (const int*)  d_in[1];   /* coors    [N,4]  */
    const float* M = (const float*)d_in[2];   /* mask     [N]    */
    const float* W = (const float*)d_in[3];   /* weight   [3,3,3,32,64] */
    float* out = (float*)d_out;

    int n = in_sizes[2];                      /* N = 400000 */
    int k = (int)((double)n * 0.5);           /* rank for threshold */
    int gpts = (n + 255) / 256;

    cudaMemsetAsync(out, 0, (size_t)out_size * sizeof(float));
    init_zero<<<(TOTZ + 255) / 256, 256>>>();

    hist_top16<<<gpts, 256>>>(M, n);
    select_pass<<<1, 256>>>(0, k);
    hist_low16<<<gpts, 256>>>(M, n);
    select_pass<<<1, 256>>>(1, 0);

    count_pairs<<<gpts, 256>>>(C, n);
    prefix27<<<1, 32>>>();
    fill_pairs<<<gpts, 256>>>(C, M, n);

    gemm_scatter<<<dim3(27, MAXCHUNK), 256>>>(F, W, out);

    mask_out<<<(NUM_OUT * 16 + 255) / 256, 256>>>(out);
}